// round 7
// baseline (speedup 1.0000x reference)
#include <cuda_runtime.h>
#include <math.h>
#include <float.h>
#include <stdint.h>

#define B_   64
#define T_   32
#define P_   64
#define E_   512
#define H_   512
#define V_   30000
#define IN_  1568
#define G4   2048      // 4*H
#define STAT 1056      // time-invariant prefix of x: [image_mean, vp, label, topic]

// ---------------- scratch (static device memory) ----------------
__device__ __align__(16) float g_image_mean[B_*E_];
__device__ __align__(16) float g_x_static[B_*STAT];
__device__ __align__(16) float g_v[B_*P_*H_];
__device__ __align__(16) float g_h[2][B_*H_];
__device__ __align__(16) float g_m[2][B_*H_];
__device__ __align__(16) float g_gates_static[B_*G4];
__device__ __align__(16) float g_emb[T_*B_*E_];
__device__ __align__(16) float g_ge[T_*B_*G4];
__device__ __align__(16) float g_gates[B_*G4];
__device__ __align__(16) float g_hs[B_*1024];
__device__ __align__(16) float g_hhs[B_*1024];
__device__ __align__(16) float g_chh[2][B_*E_];     // double-buffered (stream overlap)
__device__ __align__(16) float g_logits[2][B_*V_];  // double-buffered
__device__ __align__(16) float g_Wc[1024*E_];
__device__ __align__(16) float g_bc[1024];
__device__ __align__(16) float g_bihh[G4];
__device__ __align__(16) float g_maxlp[T_*B_];
__device__ __align__(16) float g_z[B_*65];
__device__ __align__(16) float g_pmax[B_*4];
__device__ __align__(16) float g_psum[B_*4];

// ---------------- tf32 mma helpers ----------------
__device__ __forceinline__ unsigned cvt_tf32(float x) {
    unsigned u; asm("cvt.rna.tf32.f32 %0, %1;" : "=r"(u) : "f"(x)); return u;
}
__device__ __forceinline__ void mma8(float* c, unsigned a0, unsigned a1, unsigned a2, unsigned a3,
                                     unsigned b0, unsigned b1) {
    asm volatile("mma.sync.aligned.m16n8k8.row.col.f32.tf32.tf32.f32 "
                 "{%0,%1,%2,%3}, {%4,%5,%6,%7}, {%8,%9}, {%0,%1,%2,%3};"
                 : "+f"(c[0]), "+f"(c[1]), "+f"(c[2]), "+f"(c[3])
                 : "r"(a0), "r"(a1), "r"(a2), "r"(a3), "r"(b0), "r"(b1));
}
// accurate tanh via MUFU exp: abs err ~1e-6
__device__ __forceinline__ float tanh_acc(float x) {
    float xc = fminf(fmaxf(x, -10.f), 10.f);
    float e = __expf(2.f * xc);
    return __fdividef(e - 1.f, e + 1.f);
}

// C(MxN) = act(A @ W^T + bias + addend[(m%amod)*addN + n])
// Single-pass TF32 (rel err ~1e-4 on these magnitudes; threshold 1e-3).
// M multiple of 64, K multiple of 32. Block tile 64x64, 256 threads (8 warps: 4(M) x 2(N)).
// Smem k-slot permutation: slot(k) = (k & ~7) | ((k&3)<<1) | ((k>>2)&1) so (k=t, k=t+4) adjacent.
// asplit: blocks with n0 >= asplit_n read A shifted by asplit_off columns (block-diagonal).
__global__ __launch_bounds__(256)
void mma_tf32(const float* __restrict__ A, int lda,
              const float* __restrict__ W, int ldw,
              const float* __restrict__ bias,
              const float* __restrict__ addend, int amod, int addN,
              float* __restrict__ C, int ldc, int M, int N, int K,
              int act, int asplit_n, int asplit_off)
{
    __shared__ float As[64][42];
    __shared__ float Bs[64][42];
    const int tid = threadIdx.x;
    const int m0 = blockIdx.y * 64, n0 = blockIdx.x * 64;
    if (asplit_off && n0 >= asplit_n) A += asplit_off;
    const int warp = tid >> 5, lane = tid & 31;
    const int wm = warp & 3, wn = warp >> 2;
    const int g = lane >> 2, t = lane & 3;

    float c[4][4];
#pragma unroll
    for (int i = 0; i < 4; i++)
#pragma unroll
        for (int j = 0; j < 4; j++) c[i][j] = 0.f;

    for (int kc = 0; kc < K; kc += 32) {
#pragma unroll
        for (int ii = 0; ii < 2; ii++) {
            int i = tid + ii * 256;
            int r = i >> 3, c4 = (i & 7) * 4;
            int sb = (c4 & 24) + ((c4 & 4) ? 1 : 0);
            float4 va = *(const float4*)(A + (size_t)(m0 + r) * lda + kc + c4);
            As[r][sb+0] = __uint_as_float(cvt_tf32(va.x));
            As[r][sb+2] = __uint_as_float(cvt_tf32(va.y));
            As[r][sb+4] = __uint_as_float(cvt_tf32(va.z));
            As[r][sb+6] = __uint_as_float(cvt_tf32(va.w));
            int nrow = n0 + r;
            float4 vb = (nrow < N) ? *(const float4*)(W + (size_t)nrow * ldw + kc + c4)
                                   : make_float4(0.f, 0.f, 0.f, 0.f);
            Bs[r][sb+0] = __uint_as_float(cvt_tf32(vb.x));
            Bs[r][sb+2] = __uint_as_float(cvt_tf32(vb.y));
            Bs[r][sb+4] = __uint_as_float(cvt_tf32(vb.z));
            Bs[r][sb+6] = __uint_as_float(cvt_tf32(vb.w));
        }
        __syncthreads();
#pragma unroll
        for (int j = 0; j < 4; j++) {
            const int ra = wm*16 + g, ca = j*8 + 2*t;
            float2 aLo = *(const float2*)&As[ra][ca];
            float2 aHi = *(const float2*)&As[ra + 8][ca];
            unsigned a0 = __float_as_uint(aLo.x), a1 = __float_as_uint(aHi.x);
            unsigned a2 = __float_as_uint(aLo.y), a3 = __float_as_uint(aHi.y);
#pragma unroll
            for (int nt = 0; nt < 4; nt++) {
                float2 bb = *(const float2*)&Bs[wn*32 + nt*8 + g][ca];
                mma8(c[nt], a0, a1, a2, a3, __float_as_uint(bb.x), __float_as_uint(bb.y));
            }
        }
        __syncthreads();
    }

    const int rm0 = m0 + wm*16 + g, rm1 = rm0 + 8;
#pragma unroll
    for (int nt = 0; nt < 4; nt++) {
        int cn = n0 + wn*32 + nt*8 + 2*t;
#pragma unroll
        for (int q = 0; q < 2; q++) {
            int n = cn + q;
            if (n >= N) continue;
            float bv = bias ? bias[n] : 0.f;
            float x0 = c[nt][q] + bv;
            float x1 = c[nt][2+q] + bv;
            if (addend) {
                x0 += addend[(size_t)(rm0 % amod) * addN + n];
                x1 += addend[(size_t)(rm1 % amod) * addN + n];
            }
            if (act == 1) { x0 = fmaxf(x0, 0.f); x1 = fmaxf(x1, 0.f); }
            C[(size_t)rm0 * ldc + n] = x0;
            C[(size_t)rm1 * ldc + n] = x1;
        }
    }
}

// ---------------- fp32 32x32-tile GEMM (prologue small GEMMs) ----------------
__global__ __launch_bounds__(256)
void gemm32k(const float* __restrict__ A, int lda,
             const float* __restrict__ W, int ldw,
             const float* __restrict__ bias,
             const float* __restrict__ addend, int addmod,
             float* __restrict__ C, int ldc,
             int M, int N, int K, int act,
             int asplit_n, int asplit_off)
{
    __shared__ float As[32][36];
    __shared__ float Ws[32][36];
    const int bn0 = blockIdx.x * 32;
    const int bm0 = blockIdx.y * 32;
    if (asplit_off && bn0 >= asplit_n) A += asplit_off;
    const int tid = threadIdx.x;
    const int tx = tid & 15, ty = tid >> 4;
    const int lr = tid >> 3;
    const int lq = (tid & 7) * 4;
    float acc00=0.f, acc01=0.f, acc10=0.f, acc11=0.f;

    const int am = bm0 + lr;
    const int wn = bn0 + lr;
    const float* Ap = A + (size_t)am * lda + lq;
    const float* Wp = W + (size_t)wn * ldw + lq;

    for (int k0 = 0; k0 < K; k0 += 32) {
        float4 va = (am < M) ? __ldg((const float4*)(Ap + k0)) : make_float4(0.f,0.f,0.f,0.f);
        float4 vw = (wn < N) ? __ldg((const float4*)(Wp + k0)) : make_float4(0.f,0.f,0.f,0.f);
        As[lq+0][lr] = va.x; As[lq+1][lr] = va.y; As[lq+2][lr] = va.z; As[lq+3][lr] = va.w;
        Ws[lq+0][lr] = vw.x; Ws[lq+1][lr] = vw.y; Ws[lq+2][lr] = vw.z; Ws[lq+3][lr] = vw.w;
        __syncthreads();
#pragma unroll
        for (int k = 0; k < 32; k++) {
            float2 a2 = *(const float2*)&As[k][ty*2];
            float2 b2 = *(const float2*)&Ws[k][tx*2];
            acc00 += a2.x * b2.x; acc01 += a2.x * b2.y;
            acc10 += a2.y * b2.x; acc11 += a2.y * b2.y;
        }
        __syncthreads();
    }
    float accs[2][2] = {{acc00, acc01},{acc10, acc11}};
#pragma unroll
    for (int i = 0; i < 2; i++) {
        int m = bm0 + ty*2 + i;
        if (m >= M) continue;
#pragma unroll
        for (int j = 0; j < 2; j++) {
            int n = bn0 + tx*2 + j;
            if (n >= N) continue;
            float x = accs[i][j];
            if (bias)   x += bias[n];
            if (addend) x += addend[(size_t)(addmod ? (m % addmod) : m) * N + n];
            if (act == 1)      x = fmaxf(x, 0.f);
            else if (act == 2) x = tanhf(x);
            C[(size_t)m * ldc + n] = x;
        }
    }
}

// ---------------- small kernels ----------------
__global__ void k_imean(const float* __restrict__ image)
{
    int i = blockIdx.x * blockDim.x + threadIdx.x;
    if (i >= B_*E_) return;
    int b = i >> 9, e = i & 511;
    const float* p = image + (size_t)b * P_ * E_ + e;
    float s = 0.f;
#pragma unroll 8
    for (int pp = 0; pp < P_; pp++) s += p[(size_t)pp * E_];
    g_image_mean[i] = s * (1.f / P_);
}

__global__ void k_xstatic(const float* __restrict__ vp, const float* __restrict__ lab,
                          const float* __restrict__ topic)
{
    int i = blockIdx.x * blockDim.x + threadIdx.x;
    if (i >= B_*STAT) return;
    int b = i / STAT, c = i % STAT;
    float val;
    if (c < 512)        val = g_image_mean[b*512 + c];
    else if (c < 528)   val = vp[b*16 + c - 512];
    else if (c < 544)   val = lab[b*16 + c - 528];
    else                val = topic[b*512 + c - 544];
    g_x_static[i] = val;
}

__global__ void k_prep(const float* __restrict__ fhh_w, const float* __restrict__ fhh_b,
                       const float* __restrict__ fs_w,  const float* __restrict__ fs_b,
                       const float* __restrict__ bih,   const float* __restrict__ bhh)
{
    int i = blockIdx.x * blockDim.x + threadIdx.x;
    if (i < 1024*512)
        g_Wc[i] = (i < 512*512) ? fhh_w[i] : fs_w[i - 512*512];
    if (i < 1024)
        g_bc[i] = (i < 512) ? fhh_b[i] : fs_b[i - 512];
    if (i < 2048)
        g_bihh[i] = bih[i] + bhh[i];
}

__global__ void k_emb(const int* __restrict__ text, const float* __restrict__ wemb)
{
    int i = blockIdx.x * blockDim.x + threadIdx.x;
    if (i >= T_*B_*E_) return;
    int e = i & 511;
    int r = i >> 9;
    int b = r & 63, t = r >> 6;
    int tok = (t == 0) ? 0 : text[b*T_ + (t-1)];
    g_emb[i] = wemb[(size_t)tok * E_ + e];
}

__global__ void k_lstm(int cur)
{
    int i = blockIdx.x * blockDim.x + threadIdx.x;
    if (i >= B_*H_) return;
    int b = i >> 9, h = i & 511;
    const float* g = g_gates + (size_t)b * G4;
    float ig = 1.f / (1.f + expf(-g[h]));
    float fg = 1.f / (1.f + expf(-g[h + 512]));
    float gg = tanhf(g[h + 1024]);
    float og = 1.f / (1.f + expf(-g[h + 1536]));
    float mn = fg * g_m[cur][i] + ig * gg;
    float hn = og * tanhf(mn);
    int nxt = cur ^ 1;
    g_m[nxt][i] = mn;
    g_h[nxt][i] = hn;
}

// z computation: grid (9, B); one attention position per warp
__global__ __launch_bounds__(256)
void k_attnz(const float* __restrict__ fz_w, const float* __restrict__ fz_b)
{
    int sl = blockIdx.x, b = blockIdx.y;
    __shared__ float hhsm[512];
    __shared__ float wz[512];
    int tid = threadIdx.x;
    for (int h = tid; h < 512; h += 256) { hhsm[h] = g_hhs[b*1024 + h]; wz[h] = fz_w[h]; }
    __syncthreads();
    int warp = tid >> 5, lane = tid & 31;
    int p = sl * 8 + warp;
    if (p > 64) return;
    const float* src = (p < 64) ? (g_v + ((size_t)b*64 + p) * 512)
                                : (g_hhs + b*1024 + 512);
    float s = 0.f;
    for (int h = lane; h < 512; h += 32) s += tanh_acc(src[h] + hhsm[h]) * wz[h];
#pragma unroll
    for (int o = 16; o; o >>= 1) s += __shfl_xor_sync(0xffffffffu, s, o);
    if (!lane) g_z[b*65 + p] = s + fz_b[0];
}

// softmax(z) over all 65 slots -> attn output; context c; chh = c + hh
__global__ __launch_bounds__(256)
void k_attnc(const float* __restrict__ image, float* __restrict__ out_attn, int t, int par)
{
    int b = blockIdx.x;
    __shared__ float as_[65];
    int tid = threadIdx.x;
    int warp = tid >> 5, lane = tid & 31;
    if (warp == 0) {
        float z0 = g_z[b*65 + lane];                                    // p = 0..31
        float z1 = (lane + 32 < 64) ? g_z[b*65 + lane + 32] : -FLT_MAX; // p = 32..63
        float z2 = (lane == 0) ? g_z[b*65 + 64] : -FLT_MAX;             // p = 64
        float mx = fmaxf(fmaxf(z0, z1), z2);
#pragma unroll
        for (int o = 16; o; o >>= 1) mx = fmaxf(mx, __shfl_xor_sync(0xffffffffu, mx, o));
        float e0 = expf(z0 - mx);
        float e1 = (lane + 32 < 64) ? expf(z1 - mx) : 0.f;
        float e2 = (lane == 0) ? expf(z2 - mx) : 0.f;
        float se = e0 + e1 + e2;
#pragma unroll
        for (int o = 16; o; o >>= 1) se += __shfl_xor_sync(0xffffffffu, se, o);
        float inv = 1.f / se;
        float* oat = out_attn + ((size_t)b*T_ + t)*65;
        as_[lane] = e0 * inv;  oat[lane] = e0 * inv;
        if (lane + 32 < 64) { as_[lane+32] = e1 * inv; oat[lane+32] = e1 * inv; }
        if (lane == 0)      { as_[64]     = e2 * inv; oat[64]      = e2 * inv; }
    }
    __syncthreads();
    const float* srow = g_hs + b*1024 + 512;
    const float* hh   = g_hs + b*1024;
    float* chh = g_chh[par] + b*512;
    for (int e = tid; e < 512; e += 256) {
        float c = as_[64] * srow[e];
        const float* im = image + (size_t)b * P_ * E_ + e;
#pragma unroll 8
        for (int p = 0; p < 64; p++) c += as_[p] * im[(size_t)p * E_];
        chh[e] = c + hh[e];
    }
}

// one-pass partial stats: max(x*it) and sum exp(x*it) per (b, slice of 7500)
__global__ __launch_bounds__(256)
void k_lsm1(const float* __restrict__ temp, int par)
{
    int sl = blockIdx.x, b = blockIdx.y;
    int tid = threadIdx.x;
    const float it = 1.f / temp[b];
    const float4* x4 = (const float4*)(g_logits[par] + (size_t)b*V_ + sl*7500);
    float m = -FLT_MAX, s = 0.f;
    for (int i = tid; i < 1875; i += 256) {
        float4 v = x4[i];
        float a = v.x*it, bb = v.y*it, cc = v.z*it, d = v.w*it;
        m = fmaxf(fmaxf(m, fmaxf(a, bb)), fmaxf(cc, d));
        s += __expf(a) + __expf(bb) + __expf(cc) + __expf(d);
    }
#pragma unroll
    for (int o = 16; o; o >>= 1) {
        m = fmaxf(m, __shfl_xor_sync(0xffffffffu, m, o));
        s += __shfl_xor_sync(0xffffffffu, s, o);
    }
    __shared__ float rm[8], rs[8];
    int warp = tid >> 5, lane = tid & 31;
    if (!lane) { rm[warp] = m; rs[warp] = s; }
    __syncthreads();
    if (tid == 0) {
        float M = rm[0], S = rs[0];
        for (int w = 1; w < 8; w++) { M = fmaxf(M, rm[w]); S += rs[w]; }
        g_pmax[b*4 + sl] = M;
        g_psum[b*4 + sl] = S;
    }
}

// write logp slice; record per-(t,b) max logp
__global__ __launch_bounds__(256)
void k_lsm2(const float* __restrict__ temp, float* __restrict__ out0, int t, int par)
{
    int sl = blockIdx.x, b = blockIdx.y;
    int tid = threadIdx.x;
    const float it = 1.f / temp[b];
    float S = g_psum[b*4+0] + g_psum[b*4+1] + g_psum[b*4+2] + g_psum[b*4+3];
    float logS = __logf(S);
    const float4* x4 = (const float4*)(g_logits[par] + (size_t)b*V_ + sl*7500);
    float4* o4 = (float4*)(out0 + ((size_t)b*T_ + t)*V_ + sl*7500);
    for (int i = tid; i < 1875; i += 256) {
        float4 v = x4[i];
        o4[i] = make_float4(v.x*it - logS, v.y*it - logS, v.z*it - logS, v.w*it - logS);
    }
    if (sl == 0 && tid == 0) {
        float M = fmaxf(fmaxf(g_pmax[b*4+0], g_pmax[b*4+1]), fmaxf(g_pmax[b*4+2], g_pmax[b*4+3]));
        g_maxlp[t*64 + b] = M - logS;
    }
}

__global__ void k_final(float* __restrict__ out2)
{
    int b = threadIdx.x;
    if (b >= B_) return;
    float s = 0.f;
    for (int t = 0; t < T_; t++) s += g_maxlp[t*64 + b];
    out2[b] = s;
}

// ---------------- host ----------------
extern "C" void kernel_launch(void* const* d_in, const int* in_sizes, int n_in,
                              void* d_out, int out_size)
{
    bool dictOrder = (in_sizes[5] == B_*T_);
    int o = dictOrder ? 1 : 0;
    const float* image    = (const float*)d_in[0];
    const float* vp       = (const float*)d_in[1];
    const float* label    = (const float*)d_in[2];
    const float* topic    = (const float*)d_in[3];
    const float* temp     = (const float*)d_in[4];
    const int*   text     = (const int*)(dictOrder ? d_in[5] : d_in[26]);
    const float* word_emb = (const float*)d_in[5+o];
    const float* fc_v_w   = (const float*)d_in[6+o];
    const float* fc_v_b   = (const float*)d_in[7+o];
    const float* fc_h_w   = (const float*)d_in[8+o];
    const float* fc_h_b   = (const float*)d_in[9+o];
    const float* fc_m_w   = (const float*)d_in[10+o];
    const float* fc_m_b   = (const float*)d_in[11+o];
    const float* w_ih     = (const float*)d_in[12+o];
    const float* w_hh     = (const float*)d_in[13+o];
    const float* b_ih     = (const float*)d_in[14+o];
    const float* b_hh     = (const float*)d_in[15+o];
    const float* fc_w     = (const float*)d_in[16+o];
    const float* fc_b     = (const float*)d_in[17+o];
    const float* fc_hh_w  = (const float*)d_in[18+o];
    const float* fc_hh_b  = (const float*)d_in[19+o];
    const float* fc_s_w   = (const float*)d_in[20+o];
    const float* fc_s_b   = (const float*)d_in[21+o];
    const float* fc_z_w   = (const float*)d_in[22+o];
    const float* fc_z_b   = (const float*)d_in[23+o];
    const float* fc_p_w   = (const float*)d_in[24+o];
    const float* fc_p_b   = (const float*)d_in[25+o];

    float *imean, *xstat, *vbuf, *hbuf, *mbuf, *gstat, *embp, *gep, *gates,
          *hsp, *chhp, *logitsp, *Wcp, *bcp, *bihhp, *hhsp;
    cudaGetSymbolAddress((void**)&imean,   g_image_mean);
    cudaGetSymbolAddress((void**)&xstat,   g_x_static);
    cudaGetSymbolAddress((void**)&vbuf,    g_v);
    cudaGetSymbolAddress((void**)&hbuf,    g_h);
    cudaGetSymbolAddress((void**)&mbuf,    g_m);
    cudaGetSymbolAddress((void**)&gstat,   g_gates_static);
    cudaGetSymbolAddress((void**)&embp,    g_emb);
    cudaGetSymbolAddress((void**)&gep,     g_ge);
    cudaGetSymbolAddress((void**)&gates,   g_gates);
    cudaGetSymbolAddress((void**)&hsp,     g_hs);
    cudaGetSymbolAddress((void**)&chhp,    g_chh);
    cudaGetSymbolAddress((void**)&logitsp, g_logits);
    cudaGetSymbolAddress((void**)&Wcp,     g_Wc);
    cudaGetSymbolAddress((void**)&bcp,     g_bc);
    cudaGetSymbolAddress((void**)&bihhp,   g_bihh);
    cudaGetSymbolAddress((void**)&hhsp,    g_hhs);

    float* out0 = (float*)d_out;
    float* out1 = out0 + (size_t)B_*T_*V_;
    float* out2 = out1 + (size_t)B_*T_*65;

    static cudaStream_t s2 = nullptr;
    static cudaEvent_t evA = nullptr, evEnd = nullptr, evB[2] = {nullptr, nullptr};
    if (!s2) {
        cudaStreamCreateWithFlags(&s2, cudaStreamNonBlocking);
        cudaEventCreateWithFlags(&evA, cudaEventDisableTiming);
        cudaEventCreateWithFlags(&evEnd, cudaEventDisableTiming);
        cudaEventCreateWithFlags(&evB[0], cudaEventDisableTiming);
        cudaEventCreateWithFlags(&evB[1], cudaEventDisableTiming);
    }

    // ---- prologue (stream 0) ----
    k_imean<<<(B_*E_ + 255)/256, 256>>>(image);
    k_xstatic<<<(B_*STAT + 255)/256, 256>>>(vp, label, topic);
    k_prep<<<(1024*512 + 255)/256, 256>>>(fc_hh_w, fc_hh_b, fc_s_w, fc_s_b, b_ih, b_hh);
    k_emb<<<(T_*B_*E_ + 255)/256, 256>>>(text, word_emb);

    // v = image @ fc_v_w^T + fc_v_b  (TF32)
    mma_tf32<<<dim3(E_/64, (B_*P_)/64), 256>>>(image, E_, fc_v_w, E_, fc_v_b,
                                               nullptr, 1, 0, vbuf, H_, B_*P_, H_, E_, 0, 0, 0);
    gemm32k<<<dim3(16, 2), 256>>>(imean, E_, fc_h_w, E_, fc_h_b, nullptr, 0,
                                  hbuf, H_, B_, H_, E_, 2, 0, 0);
    gemm32k<<<dim3(16, 2), 256>>>(imean, E_, fc_m_w, E_, fc_m_b, nullptr, 0,
                                  mbuf, H_, B_, H_, E_, 2, 0, 0);
    gemm32k<<<dim3(G4/32, 2), 256>>>(xstat, STAT, w_ih, IN_, bihhp, nullptr, 0,
                                     gstat, G4, B_, G4, STAT, 0, 0, 0);
    // ge[t*64+b,:] = emb @ w_ih[:,1056:]^T + gates_static[b,:]  (TF32)
    mma_tf32<<<dim3(G4/64, (T_*B_)/64), 256>>>(embp, E_, w_ih + STAT, IN_, nullptr,
                                               gstat, 64, G4, gep, G4, T_*B_, G4, E_, 0, 0, 0);

    // ---- sequential steps: recurrence on stream 0, logits+log-softmax on s2 ----
    for (int t = 0; t < T_; t++) {
        int cur = t & 1, nxt = cur ^ 1, par = t & 1;
        // gates = h @ w_hh^T + ge[t]   (TF32)
        mma_tf32<<<dim3(G4/64, 1), 256>>>(hbuf + (size_t)cur*B_*H_, H_, w_hh, H_,
                                          nullptr, gep + (size_t)t*B_*G4, 64, G4,
                                          gates, G4, B_, G4, H_, 0, 0, 0);
        k_lstm<<<(B_*H_ + 255)/256, 256>>>(cur);
        // hs = relu(h_new @ fc_w^T + fc_b)   (TF32)
        mma_tf32<<<dim3(1024/64, 1), 256>>>(hbuf + (size_t)nxt*B_*H_, H_, fc_w, H_,
                                            fc_b, nullptr, 1, 0, hsp, 1024, B_, 1024, H_, 1, 0, 0);
        // [_hh | _s] block-diagonal   (TF32)
        mma_tf32<<<dim3(1024/64, 1), 256>>>(hsp, 1024, Wcp, H_, bcp,
                                            nullptr, 1, 0, hhsp, 1024, B_, 1024, H_, 0, 512, 512);
        k_attnz<<<dim3(9, B_), 256>>>(fc_z_w, fc_z_b);
        if (t >= 2) cudaStreamWaitEvent(0, evB[par], 0);   // vocab(t-2) done reading chh[par]
        k_attnc<<<B_, 256>>>(image, out1, t, par);
        cudaEventRecord(evA, 0);

        cudaStreamWaitEvent(s2, evA, 0);
        mma_tf32<<<dim3((V_ + 63)/64, 1), 256, 0, s2>>>(chhp + (size_t)par*B_*E_, E_,
                                                        fc_p_w, E_, fc_p_b, nullptr, 1, 0,
                                                        logitsp + (size_t)par*B_*V_, V_,
                                                        B_, V_, E_, 0, 0, 0);
        cudaEventRecord(evB[par], s2);
        k_lsm1<<<dim3(4, B_), 256, 0, s2>>>(temp, par);
        k_lsm2<<<dim3(4, B_), 256, 0, s2>>>(temp, out0, t, par);
    }
    cudaEventRecord(evEnd, s2);
    cudaStreamWaitEvent(0, evEnd, 0);
    k_final<<<1, 64>>>(out2);
}

// round 8
// speedup vs baseline: 1.4192x; 1.4192x over previous
#include <cuda_runtime.h>
#include <math.h>
#include <float.h>
#include <stdint.h>

#define B_   64
#define T_   32
#define P_   64
#define E_   512
#define H_   512
#define V_   30000
#define IN_  1568
#define G4   2048      // 4*H
#define STAT 1056      // time-invariant prefix of x: [image_mean, vp, label, topic]

// ---------------- scratch (static device memory) ----------------
__device__ __align__(16) float g_image_mean[B_*E_];
__device__ __align__(16) float g_x_static[B_*STAT];
__device__ __align__(16) float g_v[B_*P_*H_];
__device__ __align__(16) float g_h[2][B_*H_];
__device__ __align__(16) float g_m[2][B_*H_];
__device__ __align__(16) float g_gates_static[B_*G4];
__device__ __align__(16) float g_emb[T_*B_*E_];
__device__ __align__(16) float g_ge[T_*B_*G4];
__device__ __align__(16) float g_gates[B_*G4];
__device__ __align__(16) float g_hs[B_*1024];
__device__ __align__(16) float g_hhs[B_*1024];
__device__ __align__(16) float g_chh[2][B_*E_];     // double-buffered (stream overlap)
__device__ __align__(16) float g_logits[2][B_*V_];  // double-buffered
__device__ __align__(16) float g_Wc[1024*E_];
__device__ __align__(16) float g_bc[1024];
__device__ __align__(16) float g_bihh[G4];
__device__ __align__(16) float g_maxlp[T_*B_];
__device__ __align__(16) float g_z[B_*65];
__device__ __align__(16) float g_pmax[B_*4];
__device__ __align__(16) float g_psum[B_*4];

// ---------------- tf32 mma helpers ----------------
__device__ __forceinline__ unsigned cvt_tf32(float x) {
    unsigned u; asm("cvt.rna.tf32.f32 %0, %1;" : "=r"(u) : "f"(x)); return u;
}
__device__ __forceinline__ void mma8(float* c, unsigned a0, unsigned a1, unsigned a2, unsigned a3,
                                     unsigned b0, unsigned b1) {
    asm volatile("mma.sync.aligned.m16n8k8.row.col.f32.tf32.tf32.f32 "
                 "{%0,%1,%2,%3}, {%4,%5,%6,%7}, {%8,%9}, {%0,%1,%2,%3};"
                 : "+f"(c[0]), "+f"(c[1]), "+f"(c[2]), "+f"(c[3])
                 : "r"(a0), "r"(a1), "r"(a2), "r"(a3), "r"(b0), "r"(b1));
}
// accurate tanh via MUFU exp: abs err ~1e-6
__device__ __forceinline__ float tanh_acc(float x) {
    float xc = fminf(fmaxf(x, -10.f), 10.f);
    float e = __expf(2.f * xc);
    return __fdividef(e - 1.f, e + 1.f);
}

// C(MxN) = A(MxK) @ W(NxK)^T + bias + addend[(m%amod)*addN + n]
// Single-pass TF32. Used ONLY for the three big GEMMs (v, ge, vocab) where
// grid size >= ~64 blocks; small per-step GEMMs stay on gemm32k (R7 post-mortem:
// mma at 32-block grids was ~5x slower than SIMT with 128-block grids).
__global__ __launch_bounds__(256)
void mma_tf32(const float* __restrict__ A, int lda,
              const float* __restrict__ W, int ldw,
              const float* __restrict__ bias,
              const float* __restrict__ addend, int amod, int addN,
              float* __restrict__ C, int ldc, int M, int N, int K)
{
    __shared__ float As[64][42];
    __shared__ float Bs[64][42];
    const int tid = threadIdx.x;
    const int m0 = blockIdx.y * 64, n0 = blockIdx.x * 64;
    const int warp = tid >> 5, lane = tid & 31;
    const int wm = warp & 3, wn = warp >> 2;
    const int g = lane >> 2, t = lane & 3;

    float c[4][4];
#pragma unroll
    for (int i = 0; i < 4; i++)
#pragma unroll
        for (int j = 0; j < 4; j++) c[i][j] = 0.f;

    for (int kc = 0; kc < K; kc += 32) {
#pragma unroll
        for (int ii = 0; ii < 2; ii++) {
            int i = tid + ii * 256;
            int r = i >> 3, c4 = (i & 7) * 4;
            int sb = (c4 & 24) + ((c4 & 4) ? 1 : 0);
            float4 va = *(const float4*)(A + (size_t)(m0 + r) * lda + kc + c4);
            As[r][sb+0] = __uint_as_float(cvt_tf32(va.x));
            As[r][sb+2] = __uint_as_float(cvt_tf32(va.y));
            As[r][sb+4] = __uint_as_float(cvt_tf32(va.z));
            As[r][sb+6] = __uint_as_float(cvt_tf32(va.w));
            int nrow = n0 + r;
            float4 vb = (nrow < N) ? *(const float4*)(W + (size_t)nrow * ldw + kc + c4)
                                   : make_float4(0.f, 0.f, 0.f, 0.f);
            Bs[r][sb+0] = __uint_as_float(cvt_tf32(vb.x));
            Bs[r][sb+2] = __uint_as_float(cvt_tf32(vb.y));
            Bs[r][sb+4] = __uint_as_float(cvt_tf32(vb.z));
            Bs[r][sb+6] = __uint_as_float(cvt_tf32(vb.w));
        }
        __syncthreads();
#pragma unroll
        for (int j = 0; j < 4; j++) {
            const int ra = wm*16 + g, ca = j*8 + 2*t;
            float2 aLo = *(const float2*)&As[ra][ca];
            float2 aHi = *(const float2*)&As[ra + 8][ca];
            unsigned a0 = __float_as_uint(aLo.x), a1 = __float_as_uint(aHi.x);
            unsigned a2 = __float_as_uint(aLo.y), a3 = __float_as_uint(aHi.y);
#pragma unroll
            for (int nt = 0; nt < 4; nt++) {
                float2 bb = *(const float2*)&Bs[wn*32 + nt*8 + g][ca];
                mma8(c[nt], a0, a1, a2, a3, __float_as_uint(bb.x), __float_as_uint(bb.y));
            }
        }
        __syncthreads();
    }

    const int rm0 = m0 + wm*16 + g, rm1 = rm0 + 8;
#pragma unroll
    for (int nt = 0; nt < 4; nt++) {
        int cn = n0 + wn*32 + nt*8 + 2*t;
#pragma unroll
        for (int q = 0; q < 2; q++) {
            int n = cn + q;
            if (n >= N) continue;
            float bv = bias ? bias[n] : 0.f;
            float x0 = c[nt][q] + bv;
            float x1 = c[nt][2+q] + bv;
            if (addend) {
                x0 += addend[(size_t)(rm0 % amod) * addN + n];
                x1 += addend[(size_t)(rm1 % amod) * addN + n];
            }
            C[(size_t)rm0 * ldc + n] = x0;
            C[(size_t)rm1 * ldc + n] = x1;
        }
    }
}

// ---------------- fp32 32x32-tile GEMM (recurrence path; 128-block grids) ----------------
__global__ __launch_bounds__(256)
void gemm32k(const float* __restrict__ A, int lda,
             const float* __restrict__ W, int ldw,
             const float* __restrict__ bias,
             const float* __restrict__ addend, int addmod,
             float* __restrict__ C, int ldc,
             int M, int N, int K, int act,
             int asplit_n, int asplit_off)
{
    __shared__ float As[32][36];
    __shared__ float Ws[32][36];
    const int bn0 = blockIdx.x * 32;
    const int bm0 = blockIdx.y * 32;
    if (asplit_off && bn0 >= asplit_n) A += asplit_off;
    const int tid = threadIdx.x;
    const int tx = tid & 15, ty = tid >> 4;
    const int lr = tid >> 3;
    const int lq = (tid & 7) * 4;
    float acc00=0.f, acc01=0.f, acc10=0.f, acc11=0.f;

    const int am = bm0 + lr;
    const int wn = bn0 + lr;
    const float* Ap = A + (size_t)am * lda + lq;
    const float* Wp = W + (size_t)wn * ldw + lq;

    for (int k0 = 0; k0 < K; k0 += 32) {
        float4 va = (am < M) ? __ldg((const float4*)(Ap + k0)) : make_float4(0.f,0.f,0.f,0.f);
        float4 vw = (wn < N) ? __ldg((const float4*)(Wp + k0)) : make_float4(0.f,0.f,0.f,0.f);
        As[lq+0][lr] = va.x; As[lq+1][lr] = va.y; As[lq+2][lr] = va.z; As[lq+3][lr] = va.w;
        Ws[lq+0][lr] = vw.x; Ws[lq+1][lr] = vw.y; Ws[lq+2][lr] = vw.z; Ws[lq+3][lr] = vw.w;
        __syncthreads();
#pragma unroll
        for (int k = 0; k < 32; k++) {
            float2 a2 = *(const float2*)&As[k][ty*2];
            float2 b2 = *(const float2*)&Ws[k][tx*2];
            acc00 += a2.x * b2.x; acc01 += a2.x * b2.y;
            acc10 += a2.y * b2.x; acc11 += a2.y * b2.y;
        }
        __syncthreads();
    }
    float accs[2][2] = {{acc00, acc01},{acc10, acc11}};
#pragma unroll
    for (int i = 0; i < 2; i++) {
        int m = bm0 + ty*2 + i;
        if (m >= M) continue;
#pragma unroll
        for (int j = 0; j < 2; j++) {
            int n = bn0 + tx*2 + j;
            if (n >= N) continue;
            float x = accs[i][j];
            if (bias)   x += bias[n];
            if (addend) x += addend[(size_t)(addmod ? (m % addmod) : m) * N + n];
            if (act == 1)      x = fmaxf(x, 0.f);
            else if (act == 2) x = tanhf(x);
            C[(size_t)m * ldc + n] = x;
        }
    }
}

// ---------------- small kernels ----------------
__global__ void k_imean(const float* __restrict__ image)
{
    int i = blockIdx.x * blockDim.x + threadIdx.x;
    if (i >= B_*E_) return;
    int b = i >> 9, e = i & 511;
    const float* p = image + (size_t)b * P_ * E_ + e;
    float s = 0.f;
#pragma unroll 8
    for (int pp = 0; pp < P_; pp++) s += p[(size_t)pp * E_];
    g_image_mean[i] = s * (1.f / P_);
}

__global__ void k_xstatic(const float* __restrict__ vp, const float* __restrict__ lab,
                          const float* __restrict__ topic)
{
    int i = blockIdx.x * blockDim.x + threadIdx.x;
    if (i >= B_*STAT) return;
    int b = i / STAT, c = i % STAT;
    float val;
    if (c < 512)        val = g_image_mean[b*512 + c];
    else if (c < 528)   val = vp[b*16 + c - 512];
    else if (c < 544)   val = lab[b*16 + c - 528];
    else                val = topic[b*512 + c - 544];
    g_x_static[i] = val;
}

__global__ void k_prep(const float* __restrict__ fhh_w, const float* __restrict__ fhh_b,
                       const float* __restrict__ fs_w,  const float* __restrict__ fs_b,
                       const float* __restrict__ bih,   const float* __restrict__ bhh)
{
    int i = blockIdx.x * blockDim.x + threadIdx.x;
    if (i < 1024*512)
        g_Wc[i] = (i < 512*512) ? fhh_w[i] : fs_w[i - 512*512];
    if (i < 1024)
        g_bc[i] = (i < 512) ? fhh_b[i] : fs_b[i - 512];
    if (i < 2048)
        g_bihh[i] = bih[i] + bhh[i];
}

__global__ void k_emb(const int* __restrict__ text, const float* __restrict__ wemb)
{
    int i = blockIdx.x * blockDim.x + threadIdx.x;
    if (i >= T_*B_*E_) return;
    int e = i & 511;
    int r = i >> 9;
    int b = r & 63, t = r >> 6;
    int tok = (t == 0) ? 0 : text[b*T_ + (t-1)];
    g_emb[i] = wemb[(size_t)tok * E_ + e];
}

__global__ void k_lstm(int cur)
{
    int i = blockIdx.x * blockDim.x + threadIdx.x;
    if (i >= B_*H_) return;
    int b = i >> 9, h = i & 511;
    const float* g = g_gates + (size_t)b * G4;
    float ig = 1.f / (1.f + expf(-g[h]));
    float fg = 1.f / (1.f + expf(-g[h + 512]));
    float gg = tanhf(g[h + 1024]);
    float og = 1.f / (1.f + expf(-g[h + 1536]));
    float mn = fg * g_m[cur][i] + ig * gg;
    float hn = og * tanhf(mn);
    int nxt = cur ^ 1;
    g_m[nxt][i] = mn;
    g_h[nxt][i] = hn;
}

// z computation: grid (9, B); one attention position per warp
__global__ __launch_bounds__(256)
void k_attnz(const float* __restrict__ fz_w, const float* __restrict__ fz_b)
{
    int sl = blockIdx.x, b = blockIdx.y;
    __shared__ float hhsm[512];
    __shared__ float wz[512];
    int tid = threadIdx.x;
    for (int h = tid; h < 512; h += 256) { hhsm[h] = g_hhs[b*1024 + h]; wz[h] = fz_w[h]; }
    __syncthreads();
    int warp = tid >> 5, lane = tid & 31;
    int p = sl * 8 + warp;
    if (p > 64) return;
    const float* src = (p < 64) ? (g_v + ((size_t)b*64 + p) * 512)
                                : (g_hhs + b*1024 + 512);
    float s = 0.f;
    for (int h = lane; h < 512; h += 32) s += tanh_acc(src[h] + hhsm[h]) * wz[h];
#pragma unroll
    for (int o = 16; o; o >>= 1) s += __shfl_xor_sync(0xffffffffu, s, o);
    if (!lane) g_z[b*65 + p] = s + fz_b[0];
}

// softmax(z) over all 65 slots -> attn output; context c; chh = c + hh
__global__ __launch_bounds__(256)
void k_attnc(const float* __restrict__ image, float* __restrict__ out_attn, int t, int par)
{
    int b = blockIdx.x;
    __shared__ float as_[65];
    int tid = threadIdx.x;
    int warp = tid >> 5, lane = tid & 31;
    if (warp == 0) {
        float z0 = g_z[b*65 + lane];                                    // p = 0..31
        float z1 = (lane + 32 < 64) ? g_z[b*65 + lane + 32] : -FLT_MAX; // p = 32..63
        float z2 = (lane == 0) ? g_z[b*65 + 64] : -FLT_MAX;             // p = 64
        float mx = fmaxf(fmaxf(z0, z1), z2);
#pragma unroll
        for (int o = 16; o; o >>= 1) mx = fmaxf(mx, __shfl_xor_sync(0xffffffffu, mx, o));
        float e0 = expf(z0 - mx);
        float e1 = (lane + 32 < 64) ? expf(z1 - mx) : 0.f;
        float e2 = (lane == 0) ? expf(z2 - mx) : 0.f;
        float se = e0 + e1 + e2;
#pragma unroll
        for (int o = 16; o; o >>= 1) se += __shfl_xor_sync(0xffffffffu, se, o);
        float inv = 1.f / se;
        float* oat = out_attn + ((size_t)b*T_ + t)*65;
        as_[lane] = e0 * inv;  oat[lane] = e0 * inv;
        if (lane + 32 < 64) { as_[lane+32] = e1 * inv; oat[lane+32] = e1 * inv; }
        if (lane == 0)      { as_[64]     = e2 * inv; oat[64]      = e2 * inv; }
    }
    __syncthreads();
    const float* srow = g_hs + b*1024 + 512;
    const float* hh   = g_hs + b*1024;
    float* chh = g_chh[par] + b*512;
    for (int e = tid; e < 512; e += 256) {
        float c = as_[64] * srow[e];
        const float* im = image + (size_t)b * P_ * E_ + e;
#pragma unroll 8
        for (int p = 0; p < 64; p++) c += as_[p] * im[(size_t)p * E_];
        chh[e] = c + hh[e];
    }
}

// one-pass partial stats: max(x*it) and sum exp(x*it) per (b, slice of 7500)
__global__ __launch_bounds__(256)
void k_lsm1(const float* __restrict__ temp, int par)
{
    int sl = blockIdx.x, b = blockIdx.y;
    int tid = threadIdx.x;
    const float it = 1.f / temp[b];
    const float4* x4 = (const float4*)(g_logits[par] + (size_t)b*V_ + sl*7500);
    float m = -FLT_MAX, s = 0.f;
    for (int i = tid; i < 1875; i += 256) {
        float4 v = x4[i];
        float a = v.x*it, bb = v.y*it, cc = v.z*it, d = v.w*it;
        m = fmaxf(fmaxf(m, fmaxf(a, bb)), fmaxf(cc, d));
        s += __expf(a) + __expf(bb) + __expf(cc) + __expf(d);
    }
#pragma unroll
    for (int o = 16; o; o >>= 1) {
        m = fmaxf(m, __shfl_xor_sync(0xffffffffu, m, o));
        s += __shfl_xor_sync(0xffffffffu, s, o);
    }
    __shared__ float rm[8], rs[8];
    int warp = tid >> 5, lane = tid & 31;
    if (!lane) { rm[warp] = m; rs[warp] = s; }
    __syncthreads();
    if (tid == 0) {
        float M = rm[0], S = rs[0];
        for (int w = 1; w < 8; w++) { M = fmaxf(M, rm[w]); S += rs[w]; }
        g_pmax[b*4 + sl] = M;
        g_psum[b*4 + sl] = S;
    }
}

// write logp slice; record per-(t,b) max logp
__global__ __launch_bounds__(256)
void k_lsm2(const float* __restrict__ temp, float* __restrict__ out0, int t, int par)
{
    int sl = blockIdx.x, b = blockIdx.y;
    int tid = threadIdx.x;
    const float it = 1.f / temp[b];
    float S = g_psum[b*4+0] + g_psum[b*4+1] + g_psum[b*4+2] + g_psum[b*4+3];
    float logS = __logf(S);
    const float4* x4 = (const float4*)(g_logits[par] + (size_t)b*V_ + sl*7500);
    float4* o4 = (float4*)(out0 + ((size_t)b*T_ + t)*V_ + sl*7500);
    for (int i = tid; i < 1875; i += 256) {
        float4 v = x4[i];
        o4[i] = make_float4(v.x*it - logS, v.y*it - logS, v.z*it - logS, v.w*it - logS);
    }
    if (sl == 0 && tid == 0) {
        float M = fmaxf(fmaxf(g_pmax[b*4+0], g_pmax[b*4+1]), fmaxf(g_pmax[b*4+2], g_pmax[b*4+3]));
        g_maxlp[t*64 + b] = M - logS;
    }
}

__global__ void k_final(float* __restrict__ out2)
{
    int b = threadIdx.x;
    if (b >= B_) return;
    float s = 0.f;
    for (int t = 0; t < T_; t++) s += g_maxlp[t*64 + b];
    out2[b] = s;
}

// ---------------- host ----------------
extern "C" void kernel_launch(void* const* d_in, const int* in_sizes, int n_in,
                              void* d_out, int out_size)
{
    bool dictOrder = (in_sizes[5] == B_*T_);
    int o = dictOrder ? 1 : 0;
    const float* image    = (const float*)d_in[0];
    const float* vp       = (const float*)d_in[1];
    const float* label    = (const float*)d_in[2];
    const float* topic    = (const float*)d_in[3];
    const float* temp     = (const float*)d_in[4];
    const int*   text     = (const int*)(dictOrder ? d_in[5] : d_in[26]);
    const float* word_emb = (const float*)d_in[5+o];
    const float* fc_v_w   = (const float*)d_in[6+o];
    const float* fc_v_b   = (const float*)d_in[7+o];
    const float* fc_h_w   = (const float*)d_in[8+o];
    const float* fc_h_b   = (const float*)d_in[9+o];
    const float* fc_m_w   = (const float*)d_in[10+o];
    const float* fc_m_b   = (const float*)d_in[11+o];
    const float* w_ih     = (const float*)d_in[12+o];
    const float* w_hh     = (const float*)d_in[13+o];
    const float* b_ih     = (const float*)d_in[14+o];
    const float* b_hh     = (const float*)d_in[15+o];
    const float* fc_w     = (const float*)d_in[16+o];
    const float* fc_b     = (const float*)d_in[17+o];
    const float* fc_hh_w  = (const float*)d_in[18+o];
    const float* fc_hh_b  = (const float*)d_in[19+o];
    const float* fc_s_w   = (const float*)d_in[20+o];
    const float* fc_s_b   = (const float*)d_in[21+o];
    const float* fc_z_w   = (const float*)d_in[22+o];
    const float* fc_z_b   = (const float*)d_in[23+o];
    const float* fc_p_w   = (const float*)d_in[24+o];
    const float* fc_p_b   = (const float*)d_in[25+o];

    float *imean, *xstat, *vbuf, *hbuf, *mbuf, *gstat, *embp, *gep, *gates,
          *hsp, *chhp, *logitsp, *Wcp, *bcp, *bihhp, *hhsp;
    cudaGetSymbolAddress((void**)&imean,   g_image_mean);
    cudaGetSymbolAddress((void**)&xstat,   g_x_static);
    cudaGetSymbolAddress((void**)&vbuf,    g_v);
    cudaGetSymbolAddress((void**)&hbuf,    g_h);
    cudaGetSymbolAddress((void**)&mbuf,    g_m);
    cudaGetSymbolAddress((void**)&gstat,   g_gates_static);
    cudaGetSymbolAddress((void**)&embp,    g_emb);
    cudaGetSymbolAddress((void**)&gep,     g_ge);
    cudaGetSymbolAddress((void**)&gates,   g_gates);
    cudaGetSymbolAddress((void**)&hsp,     g_hs);
    cudaGetSymbolAddress((void**)&chhp,    g_chh);
    cudaGetSymbolAddress((void**)&logitsp, g_logits);
    cudaGetSymbolAddress((void**)&Wcp,     g_Wc);
    cudaGetSymbolAddress((void**)&bcp,     g_bc);
    cudaGetSymbolAddress((void**)&bihhp,   g_bihh);
    cudaGetSymbolAddress((void**)&hhsp,    g_hhs);

    float* out0 = (float*)d_out;
    float* out1 = out0 + (size_t)B_*T_*V_;
    float* out2 = out1 + (size_t)B_*T_*65;

    static cudaStream_t s2 = nullptr;
    static cudaEvent_t evA = nullptr, evEnd = nullptr, evB[2] = {nullptr, nullptr};
    if (!s2) {
        cudaStreamCreateWithFlags(&s2, cudaStreamNonBlocking);
        cudaEventCreateWithFlags(&evA, cudaEventDisableTiming);
        cudaEventCreateWithFlags(&evEnd, cudaEventDisableTiming);
        cudaEventCreateWithFlags(&evB[0], cudaEventDisableTiming);
        cudaEventCreateWithFlags(&evB[1], cudaEventDisableTiming);
    }

    // ---- prologue (stream 0) ----
    k_imean<<<(B_*E_ + 255)/256, 256>>>(image);
    k_xstatic<<<(B_*STAT + 255)/256, 256>>>(vp, label, topic);
    k_prep<<<(1024*512 + 255)/256, 256>>>(fc_hh_w, fc_hh_b, fc_s_w, fc_s_b, b_ih, b_hh);
    k_emb<<<(T_*B_*E_ + 255)/256, 256>>>(text, word_emb);

    // v = image @ fc_v_w^T + fc_v_b  (TF32, 512 blocks)
    mma_tf32<<<dim3(E_/64, (B_*P_)/64), 256>>>(image, E_, fc_v_w, E_, fc_v_b,
                                               nullptr, 1, 0, vbuf, H_, B_*P_, H_, E_);
    gemm32k<<<dim3(16, 2), 256>>>(imean, E_, fc_h_w, E_, fc_h_b, nullptr, 0,
                                  hbuf, H_, B_, H_, E_, 2, 0, 0);
    gemm32k<<<dim3(16, 2), 256>>>(imean, E_, fc_m_w, E_, fc_m_b, nullptr, 0,
                                  mbuf, H_, B_, H_, E_, 2, 0, 0);
    gemm32k<<<dim3(G4/32, 2), 256>>>(xstat, STAT, w_ih, IN_, bihhp, nullptr, 0,
                                     gstat, G4, B_, G4, STAT, 0, 0, 0);
    // ge[t*64+b,:] = emb @ w_ih[:,1056:]^T + gates_static[b,:]  (TF32, 1024 blocks)
    mma_tf32<<<dim3(G4/64, (T_*B_)/64), 256>>>(embp, E_, w_ih + STAT, IN_, nullptr,
                                               gstat, 64, G4, gep, G4, T_*B_, G4, E_);

    // ---- sequential steps: recurrence on stream 0, logits+log-softmax on s2 ----
    for (int t = 0; t < T_; t++) {
        int cur = t & 1, nxt = cur ^ 1, par = t & 1;
        // gates = h @ w_hh^T + ge[t]   (fp32 SIMT, 128 blocks — R6-proven)
        gemm32k<<<dim3(G4/32, 2), 256>>>(hbuf + (size_t)cur*B_*H_, H_, w_hh, H_,
                                         nullptr, gep + (size_t)t*B_*G4, 0,
                                         gates, G4, B_, G4, H_, 0, 0, 0);
        k_lstm<<<(B_*H_ + 255)/256, 256>>>(cur);
        gemm32k<<<dim3(1024/32, 2), 256>>>(hbuf + (size_t)nxt*B_*H_, H_, fc_w, H_,
                                           fc_b, nullptr, 0, hsp, 1024, B_, 1024, H_, 1, 0, 0);
        gemm32k<<<dim3(1024/32, 2), 256>>>(hsp, 1024, Wcp, H_, bcp, nullptr, 0,
                                           hhsp, 1024, B_, 1024, H_, 0, 512, 512);
        k_attnz<<<dim3(9, B_), 256>>>(fc_z_w, fc_z_b);
        if (t >= 2) cudaStreamWaitEvent(0, evB[par], 0);   // vocab(t-2) done reading chh[par]
        k_attnc<<<B_, 256>>>(image, out1, t, par);
        cudaEventRecord(evA, 0);

        cudaStreamWaitEvent(s2, evA, 0);
        // logits = chh @ fc_p_w^T + fc_p_b   (TF32, 469 blocks)
        mma_tf32<<<dim3((V_ + 63)/64, 1), 256, 0, s2>>>(chhp + (size_t)par*B_*E_, E_,
                                                        fc_p_w, E_, fc_p_b, nullptr, 1, 0,
                                                        logitsp + (size_t)par*B_*V_, V_,
                                                        B_, V_, E_);
        cudaEventRecord(evB[par], s2);
        k_lsm1<<<dim3(4, B_), 256, 0, s2>>>(temp, par);
        k_lsm2<<<dim3(4, B_), 256, 0, s2>>>(temp, out0, t, par);
    }
    cudaEventRecord(evEnd, s2);
    cudaStreamWaitEvent(0, evEnd, 0);
    k_final<<<1, 64>>>(out2);
}